// round 9
// baseline (speedup 1.0000x reference)
#include <cuda_runtime.h>
#include <cuda_fp16.h>
#include <math.h>
#include <stdint.h>

#define B_   1024
#define T_   64
#define D_   512
#define H_   512
#define N4H  2048   // 4*H
#define KTOT 1024   // D + H
#define NCTA 128
#define TOTALC (T_ * 16)

// ---------------------------------------------------------------------------
// Scratch (device globals: allocation-free per harness rules)
// ---------------------------------------------------------------------------
__device__ __half g_wuth[(size_t)N4H * KTOT];   // [W;U]^T gate-interleaved, fp16
__device__ __half g_xh[(size_t)B_ * T_ * D_];   // x converted to fp16
__device__ __half g_h2h[2][(size_t)B_ * H_];    // double-buffered hidden (fp16)
__device__ float  g_bias_il[N4H];               // gate-interleaved bias (fp32)
__device__ unsigned int g_bar_count;            // grid barrier counter

// ---------------------------------------------------------------------------
// Helpers
// ---------------------------------------------------------------------------
__device__ __forceinline__ uint32_t smem_u32(const void* p) {
    uint32_t a;
    asm("{ .reg .u64 t; cvta.to.shared.u64 t, %1; cvt.u32.u64 %0, t; }"
        : "=r"(a) : "l"(p));
    return a;
}
#define CP_ASYNC16(dst, src) \
    asm volatile("cp.async.cg.shared.global [%0], [%1], 16;" \
                 :: "r"(dst), "l"(src) : "memory")
#define CP_COMMIT() asm volatile("cp.async.commit_group;" ::: "memory")
#define CP_WAIT1()  asm volatile("cp.async.wait_group 1;" ::: "memory")
#define CP_WAIT0()  asm volatile("cp.async.wait_group 0;" ::: "memory")

#define LDSM_X4(r0, r1, r2, r3, addr) \
    asm volatile("ldmatrix.sync.aligned.m8n8.x4.shared.b16 {%0,%1,%2,%3}, [%4];" \
                 : "=r"(r0), "=r"(r1), "=r"(r2), "=r"(r3) : "r"(addr))

__device__ __forceinline__ float tanh_fast(float x) {
    float y;
    asm("tanh.approx.f32 %0, %1;" : "=f"(y) : "f"(x));
    return y;
}
__device__ __forceinline__ float sig_fast(float x) {
    return 0.5f * tanh_fast(0.5f * x) + 0.5f;
}

__device__ __forceinline__ void mma_f16(float* c, const uint32_t* a,
                                        const uint32_t* b) {
    asm volatile(
        "mma.sync.aligned.m16n8k16.row.col.f32.f16.f16.f32 "
        "{%0,%1,%2,%3}, {%4,%5,%6,%7}, {%8,%9}, {%0,%1,%2,%3};"
        : "+f"(c[0]), "+f"(c[1]), "+f"(c[2]), "+f"(c[3])
        : "r"(a[0]), "r"(a[1]), "r"(a[2]), "r"(a[3]), "r"(b[0]), "r"(b[1]));
}

// ---------------------------------------------------------------------------
// SMEM: 3 stages (A[128x64h] stride 144B + B same) = 110592 B,
// bias slab (128 floats) at float offset 27648. Total 111104 B.
// ---------------------------------------------------------------------------
#define AS_B      144
#define STAGE_B   36864
#define B_OFF_B   18432
#define BIAS_F    27648
#define SM_BYTES  111104

struct Frag { float acc[2][8][4]; };

// Load one K-chunk (64 halves) for global chunk cc into stage s.
__device__ __forceinline__ void load_chunk(
    uint32_t smb, int s, int cc,
    const __half* __restrict__ xh,
    const __half* __restrict__ h0g, const __half* __restrict__ h1g,
    const __half* __restrict__ wuth, int row0, int col0, int tid)
{
    const int t  = cc >> 4;
    const int k0 = (cc & 15) * 64;
    const __half* hr = (t & 1) ? h1g : h0g;
    const uint32_t sa = smb + s * STAGE_B;
    const uint32_t sb = sa + B_OFF_B;
    #pragma unroll
    for (int i = 0; i < 4; i++) {
        int idx = tid + i * 256;          // 0..1023 = 128 rows x 8 groups
        int r = idx >> 3, f = idx & 7;
        const __half* asrc;
        if (k0 < D_) {
            asrc = &xh[((size_t)(row0 + r) * T_ + t) * D_ + k0 + f * 8];
        } else {
            asrc = &hr[(size_t)(row0 + r) * H_ + (k0 - D_) + f * 8];
        }
        CP_ASYNC16(sa + r * AS_B + f * 16, asrc);
        CP_ASYNC16(sb + r * AS_B + f * 16,
                   &wuth[(size_t)(col0 + r) * KTOT + k0 + f * 8]);
    }
}

// Compute one 64-k chunk from stage s. Warp tile 32x64.
__device__ __forceinline__ void compute_chunk(uint32_t smb, int s,
                                              int m0w, int n0w, int lane,
                                              Frag& fr) {
    const uint32_t aS = smb + s * STAGE_B;
    const uint32_t bS = aS + B_OFF_B;
    const int j = lane >> 3, lr = lane & 7;
    const int jr = (j & 1) << 3;
    const int jk = (j >> 1) << 4;
    const int jr2 = (j >> 1) << 3;
    const int jk2 = (j & 1) << 4;

    uint32_t a_off[2], b_off[4];
    #pragma unroll
    for (int mt = 0; mt < 2; mt++)
        a_off[mt] = aS + (m0w + mt * 16 + jr + lr) * AS_B + jk;
    #pragma unroll
    for (int np = 0; np < 4; np++)
        b_off[np] = bS + (n0w + np * 16 + jr2 + lr) * AS_B + jk2;

    #pragma unroll
    for (int kk = 0; kk < 4; kk++) {
        const int kb = kk * 32;
        uint32_t a[2][4], b[8][2];
        LDSM_X4(a[0][0], a[0][1], a[0][2], a[0][3], a_off[0] + kb);
        LDSM_X4(a[1][0], a[1][1], a[1][2], a[1][3], a_off[1] + kb);
        #pragma unroll
        for (int np = 0; np < 4; np++)
            LDSM_X4(b[2 * np][0], b[2 * np][1], b[2 * np + 1][0],
                    b[2 * np + 1][1], b_off[np] + kb);
        #pragma unroll
        for (int mt = 0; mt < 2; mt++)
            #pragma unroll
            for (int nt = 0; nt < 8; nt++)
                mma_f16(fr.acc[mt][nt], a[mt], b[nt]);
    }
}

// ---------------------------------------------------------------------------
// Persistent fused LSTM. Continuous cross-step cp.async pipeline; split grid
// barrier (arrive after epilogue, wait before h-chunk loads); gates computed
// in registers via lane-pair shfl; c state register-resident.
// ---------------------------------------------------------------------------
__global__ void __launch_bounds__(256, 1)
lstm_persistent_kernel(const __half* __restrict__ xh,
                       const __half* __restrict__ wuth,
                       const float* __restrict__ bias_il,
                       __half* __restrict__ h0g, __half* __restrict__ h1g,
                       float* __restrict__ out)
{
    extern __shared__ float sm[];
    const uint32_t smb = smem_u32(sm);

    const int tid = threadIdx.x;
    const int wid = tid >> 5, lane = tid & 31;
    const int cta = blockIdx.x;
    const int row0 = (cta >> 4) * 128;       // batch block
    const int col0 = (cta & 15) * 128;       // gate-col block
    const int m0w = (wid & 3) * 32, n0w = (wid >> 2) * 64;
    const int q = lane & 3, p = lane >> 2;
    const int mtSel = lane & 1;              // even lanes: mt=0, odd: mt=1

    // bias slab -> SMEM (128 floats)
    float4* bias4 = reinterpret_cast<float4*>(sm + BIAS_F);
    if (tid < 32)
        bias4[tid] = *reinterpret_cast<const float4*>(&bias_il[col0 + tid * 4]);

    const int rbase = row0 + m0w + mtSel * 16 + p;        // global batch row
    const int ub = (col0 >> 2) + (n0w >> 2) + (q >> 1);   // hidden-unit base
    const int bqb = (n0w >> 2) + (q >> 1);                // bias float4 base

    float cst[8][2];                         // register-resident cell state
    #pragma unroll
    for (int nt = 0; nt < 8; nt++) { cst[nt][0] = 0.0f; cst[nt][1] = 0.0f; }

    __syncthreads();

    load_chunk(smb, 0, 0, xh, h0g, h1g, wuth, row0, col0, tid);
    CP_COMMIT();
    load_chunk(smb, 1, 1, xh, h0g, h1g, wuth, row0, col0, tid);
    CP_COMMIT();

    for (int t = 0; t < T_; t++) {
        Frag fr;
        #pragma unroll
        for (int mt = 0; mt < 2; mt++)
            #pragma unroll
            for (int nt = 0; nt < 8; nt++)
                #pragma unroll
                for (int jj = 0; jj < 4; jj++) fr.acc[mt][nt][jj] = 0.0f;

        for (int i = 0; i < 16; i++) {
            const int cc = t * 16 + i;
            if (cc + 2 < TOTALC) {
                // next load is this step's first h-chunk -> wait for barrier
                if (i == 6 && tid == 0) {
                    unsigned int target = (unsigned)NCTA * t;
                    unsigned int v;
                    do {
                        asm volatile("ld.acquire.gpu.global.u32 %0, [%1];"
                                     : "=r"(v) : "l"(&g_bar_count) : "memory");
                        if (v < target) __nanosleep(64);
                    } while (v < target);
                }
                CP_WAIT1();
                __syncthreads();
                const int nc = cc + 2;
                load_chunk(smb, nc % 3, nc, xh, h0g, h1g, wuth, row0, col0, tid);
                CP_COMMIT();
            } else {
                CP_WAIT0();
                __syncthreads();
            }
            compute_chunk(smb, cc % 3, m0w, n0w, lane, fr);
        }

        // ---- register gate epilogue ----
        __half* hw = (t & 1) ? h0g : h1g;    // write buffer (t+1)&1
        #pragma unroll
        for (int nt = 0; nt < 8; nt++) {
            float4 bq = bias4[bqb + 2 * nt];
            float my[4], rv[4];
            #pragma unroll
            for (int k2 = 0; k2 < 4; k2++) {
                float s = mtSel ? fr.acc[0][nt][k2] : fr.acc[1][nt][k2];
                rv[k2] = __shfl_xor_sync(0xffffffffu, s, 1);
                my[k2] = mtSel ? fr.acc[1][nt][k2] : fr.acc[0][nt][k2];
            }
            const int u = ub + 2 * nt;
            #pragma unroll
            for (int kk = 0; kk < 2; kk++) {
                float fi = mtSel ? rv[2 * kk]     : my[2 * kk];
                float ff = mtSel ? rv[2 * kk + 1] : my[2 * kk + 1];
                float fgv = mtSel ? my[2 * kk]     : rv[2 * kk];
                float fo = mtSel ? my[2 * kk + 1] : rv[2 * kk + 1];
                float ig = sig_fast(fi + bq.x);
                float fg = sig_fast(ff + bq.y);
                float gg = tanh_fast(fgv + bq.z);
                float og = sig_fast(fo + bq.w);
                float cn = fg * cst[nt][kk] + ig * gg;
                float hn = og * tanh_fast(cn);
                cst[nt][kk] = cn;
                int r = rbase + kk * 8;
                hw[(size_t)r * H_ + u] = __float2half(hn);
                out[((size_t)r * T_ + t) * H_ + u] = hn;
            }
        }

        // barrier arrive (h writes of this step released)
        if (t + 1 < T_) {
            __syncthreads();
            if (tid == 0) {
                asm volatile("red.release.gpu.global.add.u32 [%0], 1;"
                             :: "l"(&g_bar_count) : "memory");
            }
        }
    }
}

// ---------------------------------------------------------------------------
// Prep kernels
// ---------------------------------------------------------------------------
__global__ void transpose_interleave_h_kernel(const float* __restrict__ in,
                                              __half* __restrict__ outp,
                                              int ko) {
    __shared__ float tile[32][33];
    int x0 = blockIdx.x * 32, y0 = blockIdx.y * 32;
    #pragma unroll
    for (int i = 0; i < 32; i += 8)
        tile[threadIdx.y + i][threadIdx.x] =
            in[(size_t)(y0 + threadIdx.y + i) * N4H + x0 + threadIdx.x];
    __syncthreads();
    #pragma unroll
    for (int i = 0; i < 32; i += 8) {
        int n = x0 + threadIdx.y + i;
        int nn = ((n & (H_ - 1)) << 2) | (n >> 9);
        int k = y0 + threadIdx.x;
        outp[(size_t)nn * KTOT + ko + k] =
            __float2half(tile[threadIdx.x][threadIdx.y + i]);
    }
}

__global__ void convert_x_kernel(const float4* __restrict__ x,
                                 uint4* __restrict__ xh) {
    size_t i = (size_t)blockIdx.x * blockDim.x + threadIdx.x;
    if (i >= (size_t)B_ * T_ * D_ / 8) return;
    float4 v0 = x[2 * i], v1 = x[2 * i + 1];
    __half2 h0 = __floats2half2_rn(v0.x, v0.y);
    __half2 h1 = __floats2half2_rn(v0.z, v0.w);
    __half2 h2 = __floats2half2_rn(v1.x, v1.y);
    __half2 h3 = __floats2half2_rn(v1.z, v1.w);
    uint4 o;
    o.x = *reinterpret_cast<uint32_t*>(&h0);
    o.y = *reinterpret_cast<uint32_t*>(&h1);
    o.z = *reinterpret_cast<uint32_t*>(&h2);
    o.w = *reinterpret_cast<uint32_t*>(&h3);
    xh[i] = o;
}

__global__ void bias_interleave_kernel(const float* __restrict__ bias,
                                       float* __restrict__ bil) {
    int nn = blockIdx.x * blockDim.x + threadIdx.x;
    if (nn < N4H) bil[nn] = bias[(nn >> 2) + (nn & 3) * H_];
}

__global__ void init_kernel(uint4* __restrict__ h0, unsigned int* barc) {
    int idx = blockIdx.x * blockDim.x + threadIdx.x;
    uint4 z = {0u, 0u, 0u, 0u};
    if (idx < B_ * H_ / 8) h0[idx] = z;
    if (idx == 0) *barc = 0;
}

// ---------------------------------------------------------------------------
// Launch
// ---------------------------------------------------------------------------
extern "C" void kernel_launch(void* const* d_in, const int* in_sizes, int n_in,
                              void* d_out, int out_size)
{
    const float* x    = (const float*)d_in[0];  // [B, T, D]
    const float* W    = (const float*)d_in[1];  // [D, 4H]
    const float* U    = (const float*)d_in[2];  // [H, 4H]
    const float* bias = (const float*)d_in[3];  // [4H]
    float* out = (float*)d_out;                 // [B, T, H]

    __half *wuth, *xh, *h2h;
    float* bil;
    unsigned int* barc;
    cudaGetSymbolAddress((void**)&wuth, g_wuth);
    cudaGetSymbolAddress((void**)&xh,   g_xh);
    cudaGetSymbolAddress((void**)&h2h,  g_h2h);
    cudaGetSymbolAddress((void**)&bil,  g_bias_il);
    cudaGetSymbolAddress((void**)&barc, g_bar_count);
    __half* h0 = h2h;
    __half* h1 = h2h + (size_t)B_ * H_;

    cudaFuncSetAttribute(lstm_persistent_kernel,
                         cudaFuncAttributeMaxDynamicSharedMemorySize, SM_BYTES);

    // Prep
    {
        dim3 blk(32, 8);
        dim3 grdW(N4H / 32, D_ / 32);
        dim3 grdU(N4H / 32, H_ / 32);
        transpose_interleave_h_kernel<<<grdW, blk>>>(W, wuth, 0);
        transpose_interleave_h_kernel<<<grdU, blk>>>(U, wuth, D_);
        bias_interleave_kernel<<<N4H / 256, 256>>>(bias, bil);
        size_t nx8 = (size_t)B_ * T_ * D_ / 8;
        convert_x_kernel<<<(unsigned)((nx8 + 255) / 256), 256>>>(
            (const float4*)x, (uint4*)xh);
        init_kernel<<<(B_ * H_ / 8 + 255) / 256, 256>>>((uint4*)h0, barc);
    }

    lstm_persistent_kernel<<<NCTA, 256, SM_BYTES>>>(xh, wuth, bil, h0, h1, out);
}

// round 10
// speedup vs baseline: 1.0804x; 1.0804x over previous
#include <cuda_runtime.h>
#include <cuda_fp16.h>
#include <math.h>
#include <stdint.h>

#define B_   1024
#define T_   64
#define D_   512
#define H_   512
#define N4H  2048   // 4*H
#define KTOT 1024   // D + H
#define NCTA 128
#define TOTALC (T_ * 16)

// ---------------------------------------------------------------------------
// Scratch (device globals: allocation-free per harness rules)
// ---------------------------------------------------------------------------
__device__ __half g_wuth[(size_t)N4H * KTOT];   // [W;U]^T gate-interleaved, fp16
__device__ __half g_xh[(size_t)B_ * T_ * D_];   // x converted to fp16
__device__ __half g_h2h[2][(size_t)B_ * H_];    // double-buffered hidden (fp16)
__device__ float  g_bias_il[N4H];               // gate-interleaved bias (fp32)
__device__ unsigned int g_bar_count;            // grid barrier counter

// ---------------------------------------------------------------------------
// Helpers
// ---------------------------------------------------------------------------
__device__ __forceinline__ uint32_t smem_u32(const void* p) {
    uint32_t a;
    asm("{ .reg .u64 t; cvta.to.shared.u64 t, %1; cvt.u32.u64 %0, t; }"
        : "=r"(a) : "l"(p));
    return a;
}
#define CP_ASYNC16(dst, src) \
    asm volatile("cp.async.cg.shared.global [%0], [%1], 16;" \
                 :: "r"(dst), "l"(src) : "memory")
#define CP_COMMIT() asm volatile("cp.async.commit_group;" ::: "memory")
#define CP_WAIT1()  asm volatile("cp.async.wait_group 1;" ::: "memory")
#define CP_WAIT0()  asm volatile("cp.async.wait_group 0;" ::: "memory")

#define LDSM_X4(r0, r1, r2, r3, addr) \
    asm volatile("ldmatrix.sync.aligned.m8n8.x4.shared.b16 {%0,%1,%2,%3}, [%4];" \
                 : "=r"(r0), "=r"(r1), "=r"(r2), "=r"(r3) : "r"(addr))

__device__ __forceinline__ float tanh_fast(float x) {
    float y;
    asm("tanh.approx.f32 %0, %1;" : "=f"(y) : "f"(x));
    return y;
}
__device__ __forceinline__ float sig_fast(float x) {
    return 0.5f * tanh_fast(0.5f * x) + 0.5f;
}

__device__ __forceinline__ void mma_f16(float* c, const uint32_t* a,
                                        const uint32_t* b) {
    asm volatile(
        "mma.sync.aligned.m16n8k16.row.col.f32.f16.f16.f32 "
        "{%0,%1,%2,%3}, {%4,%5,%6,%7}, {%8,%9}, {%0,%1,%2,%3};"
        : "+f"(c[0]), "+f"(c[1]), "+f"(c[2]), "+f"(c[3])
        : "r"(a[0]), "r"(a[1]), "r"(a[2]), "r"(a[3]), "r"(b[0]), "r"(b[1]));
}

// ---------------------------------------------------------------------------
// SMEM layout (bytes):
//   3 stages, each A[128x64h] stride 144B (18432B) + B same  = 110592 B
//   Z tile  [128 x 132] fp32 @ float 27648                   =  67584 B
//   c_tile  [128 x 32]  fp32 @ float 44544                   =  16384 B
//   Total 194560 B  (fits 227 KB; 1 CTA/SM)
// ---------------------------------------------------------------------------
#define AS_B      144
#define STAGE_B   36864
#define B_OFF_B   18432
#define ZTILE_F   27648
#define ZS        132
#define CTILE_F   44544
#define SM_BYTES  194560

struct Frag { float acc[2][8][4]; };

// Load one K-chunk (64 halves) for global chunk cc into stage s.
__device__ __forceinline__ void load_chunk(
    uint32_t smb, int s, int cc,
    const __half* __restrict__ xh,
    const __half* __restrict__ h0g, const __half* __restrict__ h1g,
    const __half* __restrict__ wuth, int row0, int col0, int tid)
{
    const int t  = cc >> 4;
    const int k0 = (cc & 15) * 64;
    const __half* hr = (t & 1) ? h1g : h0g;
    const uint32_t sa = smb + s * STAGE_B;
    const uint32_t sb = sa + B_OFF_B;
    #pragma unroll
    for (int i = 0; i < 4; i++) {
        int idx = tid + i * 256;          // 0..1023 = 128 rows x 8 groups
        int r = idx >> 3, f = idx & 7;
        const __half* asrc;
        if (k0 < D_) {
            asrc = &xh[((size_t)(row0 + r) * T_ + t) * D_ + k0 + f * 8];
        } else {
            asrc = &hr[(size_t)(row0 + r) * H_ + (k0 - D_) + f * 8];
        }
        CP_ASYNC16(sa + r * AS_B + f * 16, asrc);
        CP_ASYNC16(sb + r * AS_B + f * 16,
                   &wuth[(size_t)(col0 + r) * KTOT + k0 + f * 8]);
    }
}

// Compute one 64-k chunk from stage s. Warp tile 32x64.
__device__ __forceinline__ void compute_chunk(uint32_t smb, int s,
                                              int m0w, int n0w, int lane,
                                              Frag& fr) {
    const uint32_t aS = smb + s * STAGE_B;
    const uint32_t bS = aS + B_OFF_B;
    const int j = lane >> 3, lr = lane & 7;
    const int jr = (j & 1) << 3;
    const int jk = (j >> 1) << 4;
    const int jr2 = (j >> 1) << 3;
    const int jk2 = (j & 1) << 4;

    uint32_t a_off[2], b_off[4];
    #pragma unroll
    for (int mt = 0; mt < 2; mt++)
        a_off[mt] = aS + (m0w + mt * 16 + jr + lr) * AS_B + jk;
    #pragma unroll
    for (int np = 0; np < 4; np++)
        b_off[np] = bS + (n0w + np * 16 + jr2 + lr) * AS_B + jk2;

    #pragma unroll
    for (int kk = 0; kk < 4; kk++) {
        const int kb = kk * 32;
        uint32_t a[2][4], b[8][2];
        LDSM_X4(a[0][0], a[0][1], a[0][2], a[0][3], a_off[0] + kb);
        LDSM_X4(a[1][0], a[1][1], a[1][2], a[1][3], a_off[1] + kb);
        #pragma unroll
        for (int np = 0; np < 4; np++)
            LDSM_X4(b[2 * np][0], b[2 * np][1], b[2 * np + 1][0],
                    b[2 * np + 1][1], b_off[np] + kb);
        #pragma unroll
        for (int mt = 0; mt < 2; mt++)
            #pragma unroll
            for (int nt = 0; nt < 8; nt++)
                mma_f16(fr.acc[mt][nt], a[mt], b[nt]);
    }
}

// ---------------------------------------------------------------------------
// Persistent fused LSTM: continuous cross-step cp.async pipeline, split grid
// barrier (arrive after epilogue; wait hidden at i==6), SMEM Z-stage epilogue
// with fully-coalesced out/h stores, c state in SMEM c_tile.
// ---------------------------------------------------------------------------
__global__ void __launch_bounds__(256, 1)
lstm_persistent_kernel(const __half* __restrict__ xh,
                       const __half* __restrict__ wuth,
                       const float* __restrict__ bias_il,
                       __half* __restrict__ h0g, __half* __restrict__ h1g,
                       float* __restrict__ out)
{
    extern __shared__ float sm[];
    const uint32_t smb = smem_u32(sm);
    float* ztile  = sm + ZTILE_F;
    float* c_tile = sm + CTILE_F;

    const int tid = threadIdx.x;
    const int wid = tid >> 5, lane = tid & 31;
    const int cta = blockIdx.x;
    const int row0 = (cta >> 4) * 128;       // batch block
    const int col0 = (cta & 15) * 128;       // gate-col block
    const int m0w = (wid & 3) * 32, n0w = (wid >> 2) * 64;

    for (int k = tid; k < 4096; k += 256) c_tile[k] = 0.0f;

    const int g = tid & 31;                  // hidden-unit group within tile
    const int g0 = col0 >> 2;                // global hidden-unit base
    const float4 bv = *reinterpret_cast<const float4*>(&bias_il[col0 + 4 * g]);
    __syncthreads();

    __half* hb[2] = {h0g, h1g};

    load_chunk(smb, 0, 0, xh, h0g, h1g, wuth, row0, col0, tid);
    CP_COMMIT();
    load_chunk(smb, 1, 1, xh, h0g, h1g, wuth, row0, col0, tid);
    CP_COMMIT();

    for (int t = 0; t < T_; t++) {
        Frag fr;
        #pragma unroll
        for (int mt = 0; mt < 2; mt++)
            #pragma unroll
            for (int nt = 0; nt < 8; nt++)
                #pragma unroll
                for (int jj = 0; jj < 4; jj++) fr.acc[mt][nt][jj] = 0.0f;

        for (int i = 0; i < 16; i++) {
            const int cc = t * 16 + i;
            if (cc + 2 < TOTALC) {
                // next issued load is this step's first h-chunk -> barrier wait
                if (i == 6 && tid == 0) {
                    unsigned int target = (unsigned)NCTA * t;
                    unsigned int v;
                    do {
                        asm volatile("ld.acquire.gpu.global.u32 %0, [%1];"
                                     : "=r"(v) : "l"(&g_bar_count) : "memory");
                        if (v < target) __nanosleep(64);
                    } while (v < target);
                }
                CP_WAIT1();
                __syncthreads();
                const int nc = cc + 2;
                load_chunk(smb, nc % 3, nc, xh, h0g, h1g, wuth, row0, col0, tid);
                CP_COMMIT();
            } else {
                CP_WAIT0();
                __syncthreads();
            }
            compute_chunk(smb, cc % 3, m0w, n0w, lane, fr);
        }

        // Stage Z tile to SMEM (own region; no conflict with stage buffers)
        {
            const int q = lane & 3, p = lane >> 2;
            #pragma unroll
            for (int mt = 0; mt < 2; mt++) {
                #pragma unroll
                for (int nt = 0; nt < 8; nt++) {
                    int colz = n0w + nt * 8 + 2 * q;
                    int rz = m0w + mt * 16 + p;
                    *reinterpret_cast<float2*>(&ztile[rz * ZS + colz]) =
                        *reinterpret_cast<const float2*>(&fr.acc[mt][nt][0]);
                    *reinterpret_cast<float2*>(&ztile[(rz + 8) * ZS + colz]) =
                        *reinterpret_cast<const float2*>(&fr.acc[mt][nt][2]);
                }
            }
        }
        __syncthreads();

        // Gate math: thread -> (row r, unit group g); cols 4g..4g+3 = (i,f,g,o)
        __half* hw = hb[(t + 1) & 1];
        #pragma unroll
        for (int it = 0; it < 16; it++) {
            int r = it * 8 + wid;
            int b = row0 + r;
            float4 zv = *reinterpret_cast<const float4*>(&ztile[r * ZS + 4 * g]);
            float zi = zv.x + bv.x, zf = zv.y + bv.y;
            float zg = zv.z + bv.z, zo = zv.w + bv.w;
            float ig = sig_fast(zi), fg = sig_fast(zf);
            float gg = tanh_fast(zg), og = sig_fast(zo);
            float cold = c_tile[r * 32 + g];
            float cn = fg * cold + ig * gg;
            float hn = og * tanh_fast(cn);
            c_tile[r * 32 + g] = cn;
            hw[(size_t)b * H_ + g0 + g] = __float2half(hn);
            out[((size_t)b * T_ + t) * H_ + g0 + g] = hn;
        }

        // Barrier arrive (release h writes of this step)
        if (t + 1 < T_) {
            __syncthreads();
            if (tid == 0) {
                asm volatile("red.release.gpu.global.add.u32 [%0], 1;"
                             :: "l"(&g_bar_count) : "memory");
            }
        }
    }
}

// ---------------------------------------------------------------------------
// Prep kernels
// ---------------------------------------------------------------------------
__global__ void transpose_interleave_h_kernel(const float* __restrict__ in,
                                              __half* __restrict__ outp,
                                              int ko) {
    __shared__ float tile[32][33];
    int x0 = blockIdx.x * 32, y0 = blockIdx.y * 32;
    #pragma unroll
    for (int i = 0; i < 32; i += 8)
        tile[threadIdx.y + i][threadIdx.x] =
            in[(size_t)(y0 + threadIdx.y + i) * N4H + x0 + threadIdx.x];
    __syncthreads();
    #pragma unroll
    for (int i = 0; i < 32; i += 8) {
        int n = x0 + threadIdx.y + i;
        int nn = ((n & (H_ - 1)) << 2) | (n >> 9);
        int k = y0 + threadIdx.x;
        outp[(size_t)nn * KTOT + ko + k] =
            __float2half(tile[threadIdx.x][threadIdx.y + i]);
    }
}

__global__ void convert_x_kernel(const float4* __restrict__ x,
                                 uint4* __restrict__ xh) {
    size_t i = (size_t)blockIdx.x * blockDim.x + threadIdx.x;
    if (i >= (size_t)B_ * T_ * D_ / 8) return;
    float4 v0 = x[2 * i], v1 = x[2 * i + 1];
    __half2 h0 = __floats2half2_rn(v0.x, v0.y);
    __half2 h1 = __floats2half2_rn(v0.z, v0.w);
    __half2 h2 = __floats2half2_rn(v1.x, v1.y);
    __half2 h3 = __floats2half2_rn(v1.z, v1.w);
    uint4 o;
    o.x = *reinterpret_cast<uint32_t*>(&h0);
    o.y = *reinterpret_cast<uint32_t*>(&h1);
    o.z = *reinterpret_cast<uint32_t*>(&h2);
    o.w = *reinterpret_cast<uint32_t*>(&h3);
    xh[i] = o;
}

__global__ void bias_interleave_kernel(const float* __restrict__ bias,
                                       float* __restrict__ bil) {
    int nn = blockIdx.x * blockDim.x + threadIdx.x;
    if (nn < N4H) bil[nn] = bias[(nn >> 2) + (nn & 3) * H_];
}

__global__ void init_kernel(uint4* __restrict__ h0, unsigned int* barc) {
    int idx = blockIdx.x * blockDim.x + threadIdx.x;
    uint4 z = {0u, 0u, 0u, 0u};
    if (idx < B_ * H_ / 8) h0[idx] = z;
    if (idx == 0) *barc = 0;
}

// ---------------------------------------------------------------------------
// Launch
// ---------------------------------------------------------------------------
extern "C" void kernel_launch(void* const* d_in, const int* in_sizes, int n_in,
                              void* d_out, int out_size)
{
    const float* x    = (const float*)d_in[0];  // [B, T, D]
    const float* W    = (const float*)d_in[1];  // [D, 4H]
    const float* U    = (const float*)d_in[2];  // [H, 4H]
    const float* bias = (const float*)d_in[3];  // [4H]
    float* out = (float*)d_out;                 // [B, T, H]

    __half *wuth, *xh, *h2h;
    float* bil;
    unsigned int* barc;
    cudaGetSymbolAddress((void**)&wuth, g_wuth);
    cudaGetSymbolAddress((void**)&xh,   g_xh);
    cudaGetSymbolAddress((void**)&h2h,  g_h2h);
    cudaGetSymbolAddress((void**)&bil,  g_bias_il);
    cudaGetSymbolAddress((void**)&barc, g_bar_count);
    __half* h0 = h2h;
    __half* h1 = h2h + (size_t)B_ * H_;

    cudaFuncSetAttribute(lstm_persistent_kernel,
                         cudaFuncAttributeMaxDynamicSharedMemorySize, SM_BYTES);

    // Prep
    {
        dim3 blk(32, 8);
        dim3 grdW(N4H / 32, D_ / 32);
        dim3 grdU(N4H / 32, H_ / 32);
        transpose_interleave_h_kernel<<<grdW, blk>>>(W, wuth, 0);
        transpose_interleave_h_kernel<<<grdU, blk>>>(U, wuth, D_);
        bias_interleave_kernel<<<N4H / 256, 256>>>(bias, bil);
        size_t nx8 = (size_t)B_ * T_ * D_ / 8;
        convert_x_kernel<<<(unsigned)((nx8 + 255) / 256), 256>>>(
            (const float4*)x, (uint4*)xh);
        init_kernel<<<(B_ * H_ / 8 + 255) / 256, 256>>>((uint4*)h0, barc);
    }

    lstm_persistent_kernel<<<NCTA, 256, SM_BYTES>>>(xh, wuth, bil, h0, h1, out);
}

// round 11
// speedup vs baseline: 1.0883x; 1.0073x over previous
#include <cuda_runtime.h>
#include <cuda_fp16.h>
#include <math.h>
#include <stdint.h>

#define B_   1024
#define T_   64
#define D_   512
#define H_   512
#define N4H  2048   // 4*H
#define KTOT 1024   // D + H
#define NCTA 128
#define TOTALC (T_ * 16)

// ---------------------------------------------------------------------------
// Scratch (device globals: allocation-free per harness rules)
// ---------------------------------------------------------------------------
__device__ __half g_wuth[(size_t)N4H * KTOT];   // [W;U]^T gate-interleaved, fp16
__device__ __half g_xh[(size_t)B_ * T_ * D_];   // x converted to fp16
__device__ __half g_h2h[2][(size_t)B_ * H_];    // double-buffered hidden (fp16)
__device__ float  g_bias_il[N4H];               // gate-interleaved bias (fp32)
__device__ unsigned int g_bar_count;            // grid barrier counter

// ---------------------------------------------------------------------------
// Helpers
// ---------------------------------------------------------------------------
__device__ __forceinline__ uint32_t smem_u32(const void* p) {
    uint32_t a;
    asm("{ .reg .u64 t; cvta.to.shared.u64 t, %1; cvt.u32.u64 %0, t; }"
        : "=r"(a) : "l"(p));
    return a;
}
#define CP_ASYNC16(dst, src) \
    asm volatile("cp.async.cg.shared.global [%0], [%1], 16;" \
                 :: "r"(dst), "l"(src) : "memory")
#define CP_COMMIT() asm volatile("cp.async.commit_group;" ::: "memory")
#define CP_WAIT1()  asm volatile("cp.async.wait_group 1;" ::: "memory")
#define CP_WAIT0()  asm volatile("cp.async.wait_group 0;" ::: "memory")

#define LDSM_X4(r0, r1, r2, r3, addr) \
    asm volatile("ldmatrix.sync.aligned.m8n8.x4.shared.b16 {%0,%1,%2,%3}, [%4];" \
                 : "=r"(r0), "=r"(r1), "=r"(r2), "=r"(r3) : "r"(addr))

__device__ __forceinline__ float tanh_fast(float x) {
    float y;
    asm("tanh.approx.f32 %0, %1;" : "=f"(y) : "f"(x));
    return y;
}
__device__ __forceinline__ float sig_fast(float x) {
    return 0.5f * tanh_fast(0.5f * x) + 0.5f;
}

__device__ __forceinline__ void mma_f16(float* c, const uint32_t* a,
                                        const uint32_t* b) {
    asm volatile(
        "mma.sync.aligned.m16n8k16.row.col.f32.f16.f16.f32 "
        "{%0,%1,%2,%3}, {%4,%5,%6,%7}, {%8,%9}, {%0,%1,%2,%3};"
        : "+f"(c[0]), "+f"(c[1]), "+f"(c[2]), "+f"(c[3])
        : "r"(a[0]), "r"(a[1]), "r"(a[2]), "r"(a[3]), "r"(b[0]), "r"(b[1]));
}

// ---------------------------------------------------------------------------
// SMEM layout (bytes):
//   3 stages, each A[128x64h] stride 144B (18432B) + B same  = 110592 B
//   Z tile  [128 x 132] fp32 @ float 27648                   =  67584 B
//   c_tile  [128 x 32]  fp32 @ float 44544                   =  16384 B
//   Total 194560 B  (fits 227 KB; 1 CTA/SM)
// ---------------------------------------------------------------------------
#define AS_B      144
#define STAGE_B   36864
#define B_OFF_B   18432
#define ZTILE_F   27648
#define ZS        132
#define CTILE_F   44544
#define SM_BYTES  194560

struct Frag { float acc[2][8][4]; };

// Load one K-chunk (64 halves) for global chunk cc into stage s.
__device__ __forceinline__ void load_chunk(
    uint32_t smb, int s, int cc,
    const __half* __restrict__ xh,
    const __half* __restrict__ h0g, const __half* __restrict__ h1g,
    const __half* __restrict__ wuth, int row0, int col0, int tid)
{
    const int t  = cc >> 4;
    const int k0 = (cc & 15) * 64;
    const __half* hr = (t & 1) ? h1g : h0g;
    const uint32_t sa = smb + s * STAGE_B;
    const uint32_t sb = sa + B_OFF_B;
    #pragma unroll
    for (int i = 0; i < 4; i++) {
        int idx = tid + i * 256;          // 0..1023 = 128 rows x 8 groups
        int r = idx >> 3, f = idx & 7;
        const __half* asrc;
        if (k0 < D_) {
            asrc = &xh[((size_t)(row0 + r) * T_ + t) * D_ + k0 + f * 8];
        } else {
            asrc = &hr[(size_t)(row0 + r) * H_ + (k0 - D_) + f * 8];
        }
        CP_ASYNC16(sa + r * AS_B + f * 16, asrc);
        CP_ASYNC16(sb + r * AS_B + f * 16,
                   &wuth[(size_t)(col0 + r) * KTOT + k0 + f * 8]);
    }
}

// Compute one 64-k chunk from stage s. Warp tile 32x64.
// Fragment double-buffered: LDSM for kk+1 issued before the MMAs of kk, so
// shared-memory latency is covered by the tensor-pipe retirement of kk.
__device__ __forceinline__ void compute_chunk(uint32_t smb, int s,
                                              int m0w, int n0w, int lane,
                                              Frag& fr) {
    const uint32_t aS = smb + s * STAGE_B;
    const uint32_t bS = aS + B_OFF_B;
    const int j = lane >> 3, lr = lane & 7;
    const int jr = (j & 1) << 3;
    const int jk = (j >> 1) << 4;
    const int jr2 = (j >> 1) << 3;
    const int jk2 = (j & 1) << 4;

    uint32_t a_off[2], b_off[4];
    #pragma unroll
    for (int mt = 0; mt < 2; mt++)
        a_off[mt] = aS + (m0w + mt * 16 + jr + lr) * AS_B + jk;
    #pragma unroll
    for (int np = 0; np < 4; np++)
        b_off[np] = bS + (n0w + np * 16 + jr2 + lr) * AS_B + jk2;

    uint32_t a[2][2][4], b[2][8][2];   // [buf][tile][regs]

    // prime kk = 0
    LDSM_X4(a[0][0][0], a[0][0][1], a[0][0][2], a[0][0][3], a_off[0]);
    LDSM_X4(a[0][1][0], a[0][1][1], a[0][1][2], a[0][1][3], a_off[1]);
    #pragma unroll
    for (int np = 0; np < 4; np++)
        LDSM_X4(b[0][2 * np][0], b[0][2 * np][1], b[0][2 * np + 1][0],
                b[0][2 * np + 1][1], b_off[np]);

    #pragma unroll
    for (int kk = 0; kk < 4; kk++) {
        const int cur = kk & 1, nxt = cur ^ 1;
        if (kk < 3) {
            const int kb = (kk + 1) * 32;
            LDSM_X4(a[nxt][0][0], a[nxt][0][1], a[nxt][0][2], a[nxt][0][3],
                    a_off[0] + kb);
            LDSM_X4(a[nxt][1][0], a[nxt][1][1], a[nxt][1][2], a[nxt][1][3],
                    a_off[1] + kb);
            #pragma unroll
            for (int np = 0; np < 4; np++)
                LDSM_X4(b[nxt][2 * np][0], b[nxt][2 * np][1],
                        b[nxt][2 * np + 1][0], b[nxt][2 * np + 1][1],
                        b_off[np] + kb);
        }
        #pragma unroll
        for (int mt = 0; mt < 2; mt++)
            #pragma unroll
            for (int nt = 0; nt < 8; nt++)
                mma_f16(fr.acc[mt][nt], a[cur][mt], b[cur][nt]);
    }
}

// ---------------------------------------------------------------------------
// Persistent fused LSTM: continuous cross-step cp.async pipeline, split grid
// barrier (arrive after epilogue; wait hidden at i==6), SMEM Z-stage epilogue
// with fully-coalesced out/h stores, c state in SMEM c_tile.
// ---------------------------------------------------------------------------
__global__ void __launch_bounds__(256, 1)
lstm_persistent_kernel(const __half* __restrict__ xh,
                       const __half* __restrict__ wuth,
                       const float* __restrict__ bias_il,
                       __half* __restrict__ h0g, __half* __restrict__ h1g,
                       float* __restrict__ out)
{
    extern __shared__ float sm[];
    const uint32_t smb = smem_u32(sm);
    float* ztile  = sm + ZTILE_F;
    float* c_tile = sm + CTILE_F;

    const int tid = threadIdx.x;
    const int wid = tid >> 5, lane = tid & 31;
    const int cta = blockIdx.x;
    const int row0 = (cta >> 4) * 128;       // batch block
    const int col0 = (cta & 15) * 128;       // gate-col block
    const int m0w = (wid & 3) * 32, n0w = (wid >> 2) * 64;

    for (int k = tid; k < 4096; k += 256) c_tile[k] = 0.0f;

    const int g = tid & 31;                  // hidden-unit group within tile
    const int g0 = col0 >> 2;                // global hidden-unit base
    const float4 bv = *reinterpret_cast<const float4*>(&bias_il[col0 + 4 * g]);
    __syncthreads();

    __half* hb[2] = {h0g, h1g};

    load_chunk(smb, 0, 0, xh, h0g, h1g, wuth, row0, col0, tid);
    CP_COMMIT();
    load_chunk(smb, 1, 1, xh, h0g, h1g, wuth, row0, col0, tid);
    CP_COMMIT();

    for (int t = 0; t < T_; t++) {
        Frag fr;
        #pragma unroll
        for (int mt = 0; mt < 2; mt++)
            #pragma unroll
            for (int nt = 0; nt < 8; nt++)
                #pragma unroll
                for (int jj = 0; jj < 4; jj++) fr.acc[mt][nt][jj] = 0.0f;

        for (int i = 0; i < 16; i++) {
            const int cc = t * 16 + i;
            if (cc + 2 < TOTALC) {
                // next issued load is this step's first h-chunk -> barrier wait
                if (i == 6 && tid == 0) {
                    unsigned int target = (unsigned)NCTA * t;
                    unsigned int v;
                    do {
                        asm volatile("ld.acquire.gpu.global.u32 %0, [%1];"
                                     : "=r"(v) : "l"(&g_bar_count) : "memory");
                        if (v < target) __nanosleep(64);
                    } while (v < target);
                }
                CP_WAIT1();
                __syncthreads();
                const int nc = cc + 2;
                load_chunk(smb, nc % 3, nc, xh, h0g, h1g, wuth, row0, col0, tid);
                CP_COMMIT();
            } else {
                CP_WAIT0();
                __syncthreads();
            }
            compute_chunk(smb, cc % 3, m0w, n0w, lane, fr);
        }

        // Stage Z tile to SMEM (own region; no conflict with stage buffers)
        {
            const int q = lane & 3, p = lane >> 2;
            #pragma unroll
            for (int mt = 0; mt < 2; mt++) {
                #pragma unroll
                for (int nt = 0; nt < 8; nt++) {
                    int colz = n0w + nt * 8 + 2 * q;
                    int rz = m0w + mt * 16 + p;
                    *reinterpret_cast<float2*>(&ztile[rz * ZS + colz]) =
                        *reinterpret_cast<const float2*>(&fr.acc[mt][nt][0]);
                    *reinterpret_cast<float2*>(&ztile[(rz + 8) * ZS + colz]) =
                        *reinterpret_cast<const float2*>(&fr.acc[mt][nt][2]);
                }
            }
        }
        __syncthreads();

        // Gate math: thread -> (row r, unit group g); cols 4g..4g+3 = (i,f,g,o)
        __half* hw = hb[(t + 1) & 1];
        #pragma unroll
        for (int it = 0; it < 16; it++) {
            int r = it * 8 + wid;
            int b = row0 + r;
            float4 zv = *reinterpret_cast<const float4*>(&ztile[r * ZS + 4 * g]);
            float zi = zv.x + bv.x, zf = zv.y + bv.y;
            float zg = zv.z + bv.z, zo = zv.w + bv.w;
            float ig = sig_fast(zi), fg = sig_fast(zf);
            float gg = tanh_fast(zg), og = sig_fast(zo);
            float cold = c_tile[r * 32 + g];
            float cn = fg * cold + ig * gg;
            float hn = og * tanh_fast(cn);
            c_tile[r * 32 + g] = cn;
            hw[(size_t)b * H_ + g0 + g] = __float2half(hn);
            out[((size_t)b * T_ + t) * H_ + g0 + g] = hn;
        }

        // Barrier arrive (release h writes of this step)
        if (t + 1 < T_) {
            __syncthreads();
            if (tid == 0) {
                asm volatile("red.release.gpu.global.add.u32 [%0], 1;"
                             :: "l"(&g_bar_count) : "memory");
            }
        }
    }
}

// ---------------------------------------------------------------------------
// Prep kernels
// ---------------------------------------------------------------------------
__global__ void transpose_interleave_h_kernel(const float* __restrict__ in,
                                              __half* __restrict__ outp,
                                              int ko) {
    __shared__ float tile[32][33];
    int x0 = blockIdx.x * 32, y0 = blockIdx.y * 32;
    #pragma unroll
    for (int i = 0; i < 32; i += 8)
        tile[threadIdx.y + i][threadIdx.x] =
            in[(size_t)(y0 + threadIdx.y + i) * N4H + x0 + threadIdx.x];
    __syncthreads();
    #pragma unroll
    for (int i = 0; i < 32; i += 8) {
        int n = x0 + threadIdx.y + i;
        int nn = ((n & (H_ - 1)) << 2) | (n >> 9);
        int k = y0 + threadIdx.x;
        outp[(size_t)nn * KTOT + ko + k] =
            __float2half(tile[threadIdx.x][threadIdx.y + i]);
    }
}

__global__ void convert_x_kernel(const float4* __restrict__ x,
                                 uint4* __restrict__ xh) {
    size_t i = (size_t)blockIdx.x * blockDim.x + threadIdx.x;
    if (i >= (size_t)B_ * T_ * D_ / 8) return;
    float4 v0 = x[2 * i], v1 = x[2 * i + 1];
    __half2 h0 = __floats2half2_rn(v0.x, v0.y);
    __half2 h1 = __floats2half2_rn(v0.z, v0.w);
    __half2 h2 = __floats2half2_rn(v1.x, v1.y);
    __half2 h3 = __floats2half2_rn(v1.z, v1.w);
    uint4 o;
    o.x = *reinterpret_cast<uint32_t*>(&h0);
    o.y = *reinterpret_cast<uint32_t*>(&h1);
    o.z = *reinterpret_cast<uint32_t*>(&h2);
    o.w = *reinterpret_cast<uint32_t*>(&h3);
    xh[i] = o;
}

__global__ void bias_interleave_kernel(const float* __restrict__ bias,
                                       float* __restrict__ bil) {
    int nn = blockIdx.x * blockDim.x + threadIdx.x;
    if (nn < N4H) bil[nn] = bias[(nn >> 2) + (nn & 3) * H_];
}

__global__ void init_kernel(uint4* __restrict__ h0, unsigned int* barc) {
    int idx = blockIdx.x * blockDim.x + threadIdx.x;
    uint4 z = {0u, 0u, 0u, 0u};
    if (idx < B_ * H_ / 8) h0[idx] = z;
    if (idx == 0) *barc = 0;
}

// ---------------------------------------------------------------------------
// Launch
// ---------------------------------------------------------------------------
extern "C" void kernel_launch(void* const* d_in, const int* in_sizes, int n_in,
                              void* d_out, int out_size)
{
    const float* x    = (const float*)d_in[0];  // [B, T, D]
    const float* W    = (const float*)d_in[1];  // [D, 4H]
    const float* U    = (const float*)d_in[2];  // [H, 4H]
    const float* bias = (const float*)d_in[3];  // [4H]
    float* out = (float*)d_out;                 // [B, T, H]

    __half *wuth, *xh, *h2h;
    float* bil;
    unsigned int* barc;
    cudaGetSymbolAddress((void**)&wuth, g_wuth);
    cudaGetSymbolAddress((void**)&xh,   g_xh);
    cudaGetSymbolAddress((void**)&h2h,  g_h2h);
    cudaGetSymbolAddress((void**)&bil,  g_bias_il);
    cudaGetSymbolAddress((void**)&barc, g_bar_count);
    __half* h0 = h2h;
    __half* h1 = h2h + (size_t)B_ * H_;

    cudaFuncSetAttribute(lstm_persistent_kernel,
                         cudaFuncAttributeMaxDynamicSharedMemorySize, SM_BYTES);

    // Prep
    {
        dim3 blk(32, 8);
        dim3 grdW(N4H / 32, D_ / 32);
        dim3 grdU(N4H / 32, H_ / 32);
        transpose_interleave_h_kernel<<<grdW, blk>>>(W, wuth, 0);
        transpose_interleave_h_kernel<<<grdU, blk>>>(U, wuth, D_);
        bias_interleave_kernel<<<N4H / 256, 256>>>(bias, bil);
        size_t nx8 = (size_t)B_ * T_ * D_ / 8;
        convert_x_kernel<<<(unsigned)((nx8 + 255) / 256), 256>>>(
            (const float4*)x, (uint4*)xh);
        init_kernel<<<(B_ * H_ / 8 + 255) / 256, 256>>>((uint4*)h0, barc);
    }

    lstm_persistent_kernel<<<NCTA, 256, SM_BYTES>>>(xh, wuth, bil, h0, h1, out);
}

// round 14
// speedup vs baseline: 1.1040x; 1.0145x over previous
#include <cuda_runtime.h>
#include <cuda_fp16.h>
#include <math.h>
#include <stdint.h>

#define B_   1024
#define T_   64
#define D_   512
#define H_   512
#define N4H  2048   // 4*H
#define KTOT 1024   // D + H
#define NCTA 128
#define NTHR 512
#define TOTALC (T_ * 16)

// ---------------------------------------------------------------------------
// Scratch (device globals: allocation-free per harness rules)
// ---------------------------------------------------------------------------
__device__ __half g_wuth[(size_t)N4H * KTOT];   // [W;U]^T gate-interleaved, fp16
__device__ __half g_xh[(size_t)B_ * T_ * D_];   // x converted to fp16
__device__ __half g_h2h[2][(size_t)B_ * H_];    // double-buffered hidden (fp16)
__device__ float  g_bias_il[N4H];               // gate-interleaved bias (fp32)
__device__ unsigned int g_bar_count;            // grid barrier counter

// ---------------------------------------------------------------------------
// Helpers
// ---------------------------------------------------------------------------
__device__ __forceinline__ uint32_t smem_u32(const void* p) {
    uint32_t a;
    asm("{ .reg .u64 t; cvta.to.shared.u64 t, %1; cvt.u32.u64 %0, t; }"
        : "=r"(a) : "l"(p));
    return a;
}
#define CP_ASYNC16(dst, src) \
    asm volatile("cp.async.cg.shared.global [%0], [%1], 16;" \
                 :: "r"(dst), "l"(src) : "memory")
#define CP_COMMIT() asm volatile("cp.async.commit_group;" ::: "memory")
#define CP_WAIT1()  asm volatile("cp.async.wait_group 1;" ::: "memory")
#define CP_WAIT0()  asm volatile("cp.async.wait_group 0;" ::: "memory")

#define LDSM_X4(r0, r1, r2, r3, addr) \
    asm volatile("ldmatrix.sync.aligned.m8n8.x4.shared.b16 {%0,%1,%2,%3}, [%4];" \
                 : "=r"(r0), "=r"(r1), "=r"(r2), "=r"(r3) : "r"(addr))

__device__ __forceinline__ float tanh_fast(float x) {
    float y;
    asm("tanh.approx.f32 %0, %1;" : "=f"(y) : "f"(x));
    return y;
}
__device__ __forceinline__ float sig_fast(float x) {
    return 0.5f * tanh_fast(0.5f * x) + 0.5f;
}

__device__ __forceinline__ void mma_f16(float* c, const uint32_t* a,
                                        const uint32_t* b) {
    asm volatile(
        "mma.sync.aligned.m16n8k16.row.col.f32.f16.f16.f32 "
        "{%0,%1,%2,%3}, {%4,%5,%6,%7}, {%8,%9}, {%0,%1,%2,%3};"
        : "+f"(c[0]), "+f"(c[1]), "+f"(c[2]), "+f"(c[3])
        : "r"(a[0]), "r"(a[1]), "r"(a[2]), "r"(a[3]), "r"(b[0]), "r"(b[1]));
}

// ---------------------------------------------------------------------------
// SMEM layout (bytes):
//   3 stages, each A[128x64h] stride 144B (18432B) + B same  = 110592 B
//   Z tile  [128 x 132] fp32 @ float 27648                   =  67584 B
//   c_tile  [128 x 32]  fp32 @ float 44544                   =  16384 B
//   Total 194560 B  (fits 227 KB; 1 CTA/SM)
// ---------------------------------------------------------------------------
#define AS_B      144
#define STAGE_B   36864
#define B_OFF_B   18432
#define ZTILE_F   27648
#define ZS        132
#define CTILE_F   44544
#define SM_BYTES  194560

struct Frag { float acc[2][4][4]; };   // warp tile 32x32: 2 m16 x 4 n8

// Load one K-chunk (64 halves) for global chunk cc into stage s. 512 threads.
__device__ __forceinline__ void load_chunk(
    uint32_t smb, int s, int cc,
    const __half* __restrict__ xh,
    const __half* __restrict__ h0g, const __half* __restrict__ h1g,
    const __half* __restrict__ wuth, int row0, int col0, int tid)
{
    const int t  = cc >> 4;
    const int k0 = (cc & 15) * 64;
    const __half* hr = (t & 1) ? h1g : h0g;
    const uint32_t sa = smb + s * STAGE_B;
    const uint32_t sb = sa + B_OFF_B;
    #pragma unroll
    for (int i = 0; i < 2; i++) {
        int idx = tid + i * NTHR;         // 0..1023 = 128 rows x 8 groups
        int r = idx >> 3, f = idx & 7;
        const __half* asrc;
        if (k0 < D_) {
            asrc = &xh[((size_t)(row0 + r) * T_ + t) * D_ + k0 + f * 8];
        } else {
            asrc = &hr[(size_t)(row0 + r) * H_ + (k0 - D_) + f * 8];
        }
        CP_ASYNC16(sa + r * AS_B + f * 16, asrc);
        CP_ASYNC16(sb + r * AS_B + f * 16,
                   &wuth[(size_t)(col0 + r) * KTOT + k0 + f * 8]);
    }
}

// Compute one 64-k chunk from stage s. Warp tile 32x32, fragments
// double-buffered (LDSM for kk+1 issued before MMAs of kk).
__device__ __forceinline__ void compute_chunk(uint32_t smb, int s,
                                              int m0w, int n0w, int lane,
                                              Frag& fr) {
    const uint32_t aS = smb + s * STAGE_B;
    const uint32_t bS = aS + B_OFF_B;
    const int j = lane >> 3, lr = lane & 7;
    const int jr = (j & 1) << 3;
    const int jk = (j >> 1) << 4;
    const int jr2 = (j >> 1) << 3;
    const int jk2 = (j & 1) << 4;

    uint32_t a_off[2], b_off[2];
    #pragma unroll
    for (int mt = 0; mt < 2; mt++)
        a_off[mt] = aS + (m0w + mt * 16 + jr + lr) * AS_B + jk;
    #pragma unroll
    for (int np = 0; np < 2; np++)
        b_off[np] = bS + (n0w + np * 16 + jr2 + lr) * AS_B + jk2;

    uint32_t a[2][2][4], b[2][4][2];   // [buf][tile][regs]

    // prime kk = 0
    LDSM_X4(a[0][0][0], a[0][0][1], a[0][0][2], a[0][0][3], a_off[0]);
    LDSM_X4(a[0][1][0], a[0][1][1], a[0][1][2], a[0][1][3], a_off[1]);
    #pragma unroll
    for (int np = 0; np < 2; np++)
        LDSM_X4(b[0][2 * np][0], b[0][2 * np][1], b[0][2 * np + 1][0],
                b[0][2 * np + 1][1], b_off[np]);

    #pragma unroll
    for (int kk = 0; kk < 4; kk++) {
        const int cur = kk & 1, nxt = cur ^ 1;
        if (kk < 3) {
            const int kb = (kk + 1) * 32;
            LDSM_X4(a[nxt][0][0], a[nxt][0][1], a[nxt][0][2], a[nxt][0][3],
                    a_off[0] + kb);
            LDSM_X4(a[nxt][1][0], a[nxt][1][1], a[nxt][1][2], a[nxt][1][3],
                    a_off[1] + kb);
            #pragma unroll
            for (int np = 0; np < 2; np++)
                LDSM_X4(b[nxt][2 * np][0], b[nxt][2 * np][1],
                        b[nxt][2 * np + 1][0], b[nxt][2 * np + 1][1],
                        b_off[np] + kb);
        }
        #pragma unroll
        for (int mt = 0; mt < 2; mt++)
            #pragma unroll
            for (int nt = 0; nt < 4; nt++)
                mma_f16(fr.acc[mt][nt], a[cur][mt], b[cur][nt]);
    }
}

// ---------------------------------------------------------------------------
// Persistent fused LSTM: 512 threads (4 warps/SMSP), warp tile 32x32.
// Continuous cross-step cp.async pipeline, split grid barrier, SMEM Z-stage
// epilogue with coalesced stores, c state in SMEM.
// ---------------------------------------------------------------------------
__global__ void __launch_bounds__(NTHR, 1)
lstm_persistent_kernel(const __half* __restrict__ xh,
                       const __half* __restrict__ wuth,
                       const float* __restrict__ bias_il,
                       __half* __restrict__ h0g, __half* __restrict__ h1g,
                       float* __restrict__ out)
{
    extern __shared__ float sm[];
    const uint32_t smb = smem_u32(sm);
    float* ztile  = sm + ZTILE_F;
    float* c_tile = sm + CTILE_F;

    const int tid = threadIdx.x;
    const int wid = tid >> 5, lane = tid & 31;
    const int cta = blockIdx.x;
    const int row0 = (cta >> 4) * 128;       // batch block
    const int col0 = (cta & 15) * 128;       // gate-col block
    const int m0w = (wid & 3) * 32, n0w = (wid >> 2) * 32;

    for (int k = tid; k < 4096; k += NTHR) c_tile[k] = 0.0f;

    const int g = tid & 31;                  // hidden-unit group within tile
    const int g0 = col0 >> 2;                // global hidden-unit base
    const float4 bv = *reinterpret_cast<const float4*>(&bias_il[col0 + 4 * g]);
    __syncthreads();

    __half* hb[2] = {h0g, h1g};

    load_chunk(smb, 0, 0, xh, h0g, h1g, wuth, row0, col0, tid);
    CP_COMMIT();
    load_chunk(smb, 1, 1, xh, h0g, h1g, wuth, row0, col0, tid);
    CP_COMMIT();

    for (int t = 0; t < T_; t++) {
        Frag fr;
        #pragma unroll
        for (int mt = 0; mt < 2; mt++)
            #pragma unroll
            for (int nt = 0; nt < 4; nt++)
                #pragma unroll
                for (int jj = 0; jj < 4; jj++) fr.acc[mt][nt][jj] = 0.0f;

        for (int i = 0; i < 16; i++) {
            const int cc = t * 16 + i;
            if (cc + 2 < TOTALC) {
                // next issued load is this step's first h-chunk -> barrier wait
                if (i == 6 && tid == 0) {
                    unsigned int target = (unsigned)NCTA * t;
                    unsigned int v;
                    do {
                        asm volatile("ld.acquire.gpu.global.u32 %0, [%1];"
                                     : "=r"(v) : "l"(&g_bar_count) : "memory");
                        if (v < target) __nanosleep(64);
                    } while (v < target);
                }
                CP_WAIT1();
                __syncthreads();
                const int nc = cc + 2;
                load_chunk(smb, nc % 3, nc, xh, h0g, h1g, wuth, row0, col0, tid);
                CP_COMMIT();
            } else {
                CP_WAIT0();
                __syncthreads();
            }
            compute_chunk(smb, cc % 3, m0w, n0w, lane, fr);
        }

        // Stage Z tile to SMEM (own region; no conflict with stage buffers)
        {
            const int q = lane & 3, p = lane >> 2;
            #pragma unroll
            for (int mt = 0; mt < 2; mt++) {
                #pragma unroll
                for (int nt = 0; nt < 4; nt++) {
                    int colz = n0w + nt * 8 + 2 * q;
                    int rz = m0w + mt * 16 + p;
                    *reinterpret_cast<float2*>(&ztile[rz * ZS + colz]) =
                        *reinterpret_cast<const float2*>(&fr.acc[mt][nt][0]);
                    *reinterpret_cast<float2*>(&ztile[(rz + 8) * ZS + colz]) =
                        *reinterpret_cast<const float2*>(&fr.acc[mt][nt][2]);
                }
            }
        }
        __syncthreads();

        // Gate math: thread -> (row r, unit group g); cols 4g..4g+3 = (i,f,g,o)
        __half* hw = hb[(t + 1) & 1];
        #pragma unroll
        for (int it = 0; it < 8; it++) {
            int r = it * 16 + wid;
            int b = row0 + r;
            float4 zv = *reinterpret_cast<const float4*>(&ztile[r * ZS + 4 * g]);
            float zi = zv.x + bv.x, zf = zv.y + bv.y;
            float zg = zv.z + bv.z, zo = zv.w + bv.w;
            float ig = sig_fast(zi), fg = sig_fast(zf);
            float gg = tanh_fast(zg), og = sig_fast(zo);
            float cold = c_tile[r * 32 + g];
            float cn = fg * cold + ig * gg;
            float hn = og * tanh_fast(cn);
            c_tile[r * 32 + g] = cn;
            hw[(size_t)b * H_ + g0 + g] = __float2half(hn);
            out[((size_t)b * T_ + t) * H_ + g0 + g] = hn;
        }

        // Barrier arrive (release h writes of this step)
        if (t + 1 < T_) {
            __syncthreads();
            if (tid == 0) {
                asm volatile("red.release.gpu.global.add.u32 [%0], 1;"
                             :: "l"(&g_bar_count) : "memory");
            }
        }
    }
}

// ---------------------------------------------------------------------------
// Prep kernels
// ---------------------------------------------------------------------------
__global__ void transpose_interleave_h_kernel(const float* __restrict__ in,
                                              __half* __restrict__ outp,
                                              int ko) {
    __shared__ float tile[32][33];
    int x0 = blockIdx.x * 32, y0 = blockIdx.y * 32;
    #pragma unroll
    for (int i = 0; i < 32; i += 8)
        tile[threadIdx.y + i][threadIdx.x] =
            in[(size_t)(y0 + threadIdx.y + i) * N4H + x0 + threadIdx.x];
    __syncthreads();
    #pragma unroll
    for (int i = 0; i < 32; i += 8) {
        int n = x0 + threadIdx.y + i;
        int nn = ((n & (H_ - 1)) << 2) | (n >> 9);
        int k = y0 + threadIdx.x;
        outp[(size_t)nn * KTOT + ko + k] =
            __float2half(tile[threadIdx.x][threadIdx.y + i]);
    }
}

__global__ void convert_x_kernel(const float4* __restrict__ x,
                                 uint4* __restrict__ xh) {
    size_t i = (size_t)blockIdx.x * blockDim.x + threadIdx.x;
    if (i >= (size_t)B_ * T_ * D_ / 8) return;
    float4 v0 = x[2 * i], v1 = x[2 * i + 1];
    __half2 h0 = __floats2half2_rn(v0.x, v0.y);
    __half2 h1 = __floats2half2_rn(v0.z, v0.w);
    __half2 h2 = __floats2half2_rn(v1.x, v1.y);
    __half2 h3 = __floats2half2_rn(v1.z, v1.w);
    uint4 o;
    o.x = *reinterpret_cast<uint32_t*>(&h0);
    o.y = *reinterpret_cast<uint32_t*>(&h1);
    o.z = *reinterpret_cast<uint32_t*>(&h2);
    o.w = *reinterpret_cast<uint32_t*>(&h3);
    xh[i] = o;
}

__global__ void bias_interleave_kernel(const float* __restrict__ bias,
                                       float* __restrict__ bil) {
    int nn = blockIdx.x * blockDim.x + threadIdx.x;
    if (nn < N4H) bil[nn] = bias[(nn >> 2) + (nn & 3) * H_];
}

__global__ void init_kernel(uint4* __restrict__ h0, unsigned int* barc) {
    int idx = blockIdx.x * blockDim.x + threadIdx.x;
    uint4 z = {0u, 0u, 0u, 0u};
    if (idx < B_ * H_ / 8) h0[idx] = z;
    if (idx == 0) *barc = 0;
}

// ---------------------------------------------------------------------------
// Launch
// ---------------------------------------------------------------------------
extern "C" void kernel_launch(void* const* d_in, const int* in_sizes, int n_in,
                              void* d_out, int out_size)
{
    const float* x    = (const float*)d_in[0];  // [B, T, D]
    const float* W    = (const float*)d_in[1];  // [D, 4H]
    const float* U    = (const float*)d_in[2];  // [H, 4H]
    const float* bias = (const float*)d_in[3];  // [4H]
    float* out = (float*)d_out;                 // [B, T, H]

    __half *wuth, *xh, *h2h;
    float* bil;
    unsigned int* barc;
    cudaGetSymbolAddress((void**)&wuth, g_wuth);
    cudaGetSymbolAddress((void**)&xh,   g_xh);
    cudaGetSymbolAddress((void**)&h2h,  g_h2h);
    cudaGetSymbolAddress((void**)&bil,  g_bias_il);
    cudaGetSymbolAddress((void**)&barc, g_bar_count);
    __half* h0 = h2h;
    __half* h1 = h2h + (size_t)B_ * H_;

    cudaFuncSetAttribute(lstm_persistent_kernel,
                         cudaFuncAttributeMaxDynamicSharedMemorySize, SM_BYTES);

    // Prep
    {
        dim3 blk(32, 8);
        dim3 grdW(N4H / 32, D_ / 32);
        dim3 grdU(N4H / 32, H_ / 32);
        transpose_interleave_h_kernel<<<grdW, blk>>>(W, wuth, 0);
        transpose_interleave_h_kernel<<<grdU, blk>>>(U, wuth, D_);
        bias_interleave_kernel<<<N4H / 256, 256>>>(bias, bil);
        size_t nx8 = (size_t)B_ * T_ * D_ / 8;
        convert_x_kernel<<<(unsigned)((nx8 + 255) / 256), 256>>>(
            (const float4*)x, (uint4*)xh);
        init_kernel<<<(B_ * H_ / 8 + 255) / 256, 256>>>((uint4*)h0, barc);
    }

    lstm_persistent_kernel<<<NCTA, NTHR, SM_BYTES>>>(xh, wuth, bil, h0, h1, out);
}

// round 16
// speedup vs baseline: 1.1163x; 1.0111x over previous
#include <cuda_runtime.h>
#include <cuda_fp16.h>
#include <math.h>
#include <stdint.h>

#define B_   1024
#define T_   64
#define D_   512
#define H_   512
#define N4H  2048   // 4*H
#define KTOT 1024   // D + H
#define NCTA 256    // 2 CTAs per SM
#define NTHR 256
#define TOTALC (T_ * 16)

// ---------------------------------------------------------------------------
// Scratch (device globals: allocation-free per harness rules)
// ---------------------------------------------------------------------------
__device__ __half g_wuth[(size_t)N4H * KTOT];   // [W;U]^T gate-interleaved, fp16
__device__ __half g_xh[(size_t)B_ * T_ * D_];   // x converted to fp16
__device__ __half g_h2h[2][(size_t)B_ * H_];    // double-buffered hidden (fp16)
__device__ float  g_bias_il[N4H];               // gate-interleaved bias (fp32)
__device__ unsigned int g_bar_count;            // grid barrier counter

// ---------------------------------------------------------------------------
// Helpers
// ---------------------------------------------------------------------------
__device__ __forceinline__ uint32_t smem_u32(const void* p) {
    uint32_t a;
    asm("{ .reg .u64 t; cvta.to.shared.u64 t, %1; cvt.u32.u64 %0, t; }"
        : "=r"(a) : "l"(p));
    return a;
}
#define CP_ASYNC16(dst, src) \
    asm volatile("cp.async.cg.shared.global [%0], [%1], 16;" \
                 :: "r"(dst), "l"(src) : "memory")
#define CP_COMMIT() asm volatile("cp.async.commit_group;" ::: "memory")
#define CP_WAIT1()  asm volatile("cp.async.wait_group 1;" ::: "memory")
#define CP_WAIT0()  asm volatile("cp.async.wait_group 0;" ::: "memory")

#define LDSM_X4(r0, r1, r2, r3, addr) \
    asm volatile("ldmatrix.sync.aligned.m8n8.x4.shared.b16 {%0,%1,%2,%3}, [%4];" \
                 : "=r"(r0), "=r"(r1), "=r"(r2), "=r"(r3) : "r"(addr))

__device__ __forceinline__ float tanh_fast(float x) {
    float y;
    asm("tanh.approx.f32 %0, %1;" : "=f"(y) : "f"(x));
    return y;
}
__device__ __forceinline__ float sig_fast(float x) {
    return 0.5f * tanh_fast(0.5f * x) + 0.5f;
}

__device__ __forceinline__ void mma_f16(float* c, const uint32_t* a,
                                        const uint32_t* b) {
    asm volatile(
        "mma.sync.aligned.m16n8k16.row.col.f32.f16.f16.f32 "
        "{%0,%1,%2,%3}, {%4,%5,%6,%7}, {%8,%9}, {%0,%1,%2,%3};"
        : "+f"(c[0]), "+f"(c[1]), "+f"(c[2]), "+f"(c[3])
        : "r"(a[0]), "r"(a[1]), "r"(a[2]), "r"(a[3]), "r"(b[0]), "r"(b[1]));
}

// ---------------------------------------------------------------------------
// SMEM layout per CTA (bytes), CTA tile = 64 (batch rows) x 128 (gate cols):
//   3 stages, each: A[64 x 64h] stride 144B (9216B) + B[128 x 64h] (18432B)
//                   = 27648B/stage -> 82944 B
//   Z half-tile [32 x 132] fp32 @ 82944                    = 16896 B
//   c_tile [64 x 32] fp32 @ 99840                          =  8192 B
//   Total 108032 B -> 2 CTAs/SM = 216064 B < 227 KB
// ---------------------------------------------------------------------------
#define AS_B      144
#define STAGE_B   27648
#define B_OFF_B   9216
#define ZTILE_F   20736      // 82944/4
#define ZS        132
#define CTILE_F   24960      // 99840/4
#define SM_BYTES  108032

struct Frag { float acc[2][4][4]; };   // warp tile 32x32: 2 m16 x 4 n8

// Load one K-chunk (64 halves) for global chunk cc into stage s. 256 threads.
// A: 64 rows x 8 groups = 512 cp.async; B: 128 rows x 8 = 1024. 6 per thread.
__device__ __forceinline__ void load_chunk(
    uint32_t smb, int s, int cc,
    const __half* __restrict__ xh,
    const __half* __restrict__ h0g, const __half* __restrict__ h1g,
    const __half* __restrict__ wuth, int row0, int col0, int tid)
{
    const int t  = cc >> 4;
    const int k0 = (cc & 15) * 64;
    const __half* hr = (t & 1) ? h1g : h0g;
    const uint32_t sa = smb + s * STAGE_B;
    const uint32_t sb = sa + B_OFF_B;
    #pragma unroll
    for (int i = 0; i < 6; i++) {
        int idx = tid + i * NTHR;         // 0..1535
        if (idx < 512) {
            int r = idx >> 3, f = idx & 7;
            const __half* asrc;
            if (k0 < D_) {
                asrc = &xh[((size_t)(row0 + r) * T_ + t) * D_ + k0 + f * 8];
            } else {
                asrc = &hr[(size_t)(row0 + r) * H_ + (k0 - D_) + f * 8];
            }
            CP_ASYNC16(sa + r * AS_B + f * 16, asrc);
        } else {
            int e = idx - 512;
            int rb = e >> 3, f = e & 7;
            CP_ASYNC16(sb + rb * AS_B + f * 16,
                       &wuth[(size_t)(col0 + rb) * KTOT + k0 + f * 8]);
        }
    }
}

// Compute one 64-k chunk from stage s. Warp tile 32x32, fragments
// double-buffered (LDSM for kk+1 issued before MMAs of kk).
__device__ __forceinline__ void compute_chunk(uint32_t smb, int s,
                                              int m0w, int n0w, int lane,
                                              Frag& fr) {
    const uint32_t aS = smb + s * STAGE_B;
    const uint32_t bS = aS + B_OFF_B;
    const int j = lane >> 3, lr = lane & 7;
    const int jr = (j & 1) << 3;
    const int jk = (j >> 1) << 4;
    const int jr2 = (j >> 1) << 3;
    const int jk2 = (j & 1) << 4;

    uint32_t a_off[2], b_off[2];
    #pragma unroll
    for (int mt = 0; mt < 2; mt++)
        a_off[mt] = aS + (m0w + mt * 16 + jr + lr) * AS_B + jk;
    #pragma unroll
    for (int np = 0; np < 2; np++)
        b_off[np] = bS + (n0w + np * 16 + jr2 + lr) * AS_B + jk2;

    uint32_t a[2][2][4], b[2][4][2];   // [buf][tile][regs]

    // prime kk = 0
    LDSM_X4(a[0][0][0], a[0][0][1], a[0][0][2], a[0][0][3], a_off[0]);
    LDSM_X4(a[0][1][0], a[0][1][1], a[0][1][2], a[0][1][3], a_off[1]);
    #pragma unroll
    for (int np = 0; np < 2; np++)
        LDSM_X4(b[0][2 * np][0], b[0][2 * np][1], b[0][2 * np + 1][0],
                b[0][2 * np + 1][1], b_off[np]);

    #pragma unroll
    for (int kk = 0; kk < 4; kk++) {
        const int cur = kk & 1, nxt = cur ^ 1;
        if (kk < 3) {
            const int kb = (kk + 1) * 32;
            LDSM_X4(a[nxt][0][0], a[nxt][0][1], a[nxt][0][2], a[nxt][0][3],
                    a_off[0] + kb);
            LDSM_X4(a[nxt][1][0], a[nxt][1][1], a[nxt][1][2], a[nxt][1][3],
                    a_off[1] + kb);
            #pragma unroll
            for (int np = 0; np < 2; np++)
                LDSM_X4(b[nxt][2 * np][0], b[nxt][2 * np][1],
                        b[nxt][2 * np + 1][0], b[nxt][2 * np + 1][1],
                        b_off[np] + kb);
        }
        #pragma unroll
        for (int mt = 0; mt < 2; mt++)
            #pragma unroll
            for (int nt = 0; nt < 4; nt++)
                mma_f16(fr.acc[mt][nt], a[cur][mt], b[cur][nt]);
    }
}

// ---------------------------------------------------------------------------
// Persistent fused LSTM: 256 CTAs (2/SM), CTA tile 64x128, 8 warps (2x4 grid).
// Continuous cross-step cp.async pipeline, split grid barrier, two-phase SMEM
// Z epilogue with coalesced stores, c state in SMEM.
// ---------------------------------------------------------------------------
__global__ void __launch_bounds__(NTHR, 2)
lstm_persistent_kernel(const __half* __restrict__ xh,
                       const __half* __restrict__ wuth,
                       const float* __restrict__ bias_il,
                       __half* __restrict__ h0g, __half* __restrict__ h1g,
                       float* __restrict__ out)
{
    extern __shared__ float sm[];
    const uint32_t smb = smem_u32(sm);
    float* ztile  = sm + ZTILE_F;
    float* c_tile = sm + CTILE_F;

    const int tid = threadIdx.x;
    const int wid = tid >> 5, lane = tid & 31;
    const int cta = blockIdx.x;
    const int row0 = (cta >> 4) * 64;        // batch block (16 x 64 rows)
    const int col0 = (cta & 15) * 128;       // gate-col block
    const int m0w = (wid & 1) * 32, n0w = (wid >> 1) * 32;

    for (int k = tid; k < 2048; k += NTHR) c_tile[k] = 0.0f;

    const int g = tid & 31;                  // hidden-unit group within tile
    const int g0 = col0 >> 2;                // global hidden-unit base
    const float4 bv = *reinterpret_cast<const float4*>(&bias_il[col0 + 4 * g]);
    __syncthreads();

    __half* hb[2] = {h0g, h1g};

    load_chunk(smb, 0, 0, xh, h0g, h1g, wuth, row0, col0, tid);
    CP_COMMIT();
    load_chunk(smb, 1, 1, xh, h0g, h1g, wuth, row0, col0, tid);
    CP_COMMIT();

    for (int t = 0; t < T_; t++) {
        Frag fr;
        #pragma unroll
        for (int mt = 0; mt < 2; mt++)
            #pragma unroll
            for (int nt = 0; nt < 4; nt++)
                #pragma unroll
                for (int jj = 0; jj < 4; jj++) fr.acc[mt][nt][jj] = 0.0f;

        for (int i = 0; i < 16; i++) {
            const int cc = t * 16 + i;
            if (cc + 2 < TOTALC) {
                // next issued load is this step's first h-chunk -> barrier wait
                if (i == 6 && tid == 0) {
                    unsigned int target = (unsigned)NCTA * t;
                    unsigned int v;
                    do {
                        asm volatile("ld.acquire.gpu.global.u32 %0, [%1];"
                                     : "=r"(v) : "l"(&g_bar_count) : "memory");
                        if (v < target) __nanosleep(64);
                    } while (v < target);
                }
                CP_WAIT1();
                __syncthreads();
                const int nc = cc + 2;
                load_chunk(smb, nc % 3, nc, xh, h0g, h1g, wuth, row0, col0, tid);
                CP_COMMIT();
            } else {
                CP_WAIT0();
                __syncthreads();
            }
            compute_chunk(smb, cc % 3, m0w, n0w, lane, fr);
        }

        // ---- two-phase epilogue (Z half-tile = 32 rows) ----
        __half* hw = hb[(t + 1) & 1];
        #pragma unroll
        for (int ph = 0; ph < 2; ph++) {
            if (m0w == ph * 32) {
                const int q = lane & 3, p = lane >> 2;
                #pragma unroll
                for (int mt = 0; mt < 2; mt++) {
                    #pragma unroll
                    for (int nt = 0; nt < 4; nt++) {
                        int colz = n0w + nt * 8 + 2 * q;
                        int rz = mt * 16 + p;          // 0..31 within phase
                        *reinterpret_cast<float2*>(&ztile[rz * ZS + colz]) =
                            *reinterpret_cast<const float2*>(&fr.acc[mt][nt][0]);
                        *reinterpret_cast<float2*>(&ztile[(rz + 8) * ZS + colz]) =
                            *reinterpret_cast<const float2*>(&fr.acc[mt][nt][2]);
                    }
                }
            }
            __syncthreads();
            // gate math on rows [ph*32, ph*32+32)
            #pragma unroll
            for (int it = 0; it < 4; it++) {
                int rl = it * 8 + wid;               // 0..31
                int r = ph * 32 + rl;                // 0..63 within CTA
                int b = row0 + r;
                float4 zv =
                    *reinterpret_cast<const float4*>(&ztile[rl * ZS + 4 * g]);
                float zi = zv.x + bv.x, zf = zv.y + bv.y;
                float zg = zv.z + bv.z, zo = zv.w + bv.w;
                float ig = sig_fast(zi), fg = sig_fast(zf);
                float gg = tanh_fast(zg), og = sig_fast(zo);
                float cold = c_tile[r * 32 + g];
                float cn = fg * cold + ig * gg;
                float hn = og * tanh_fast(cn);
                c_tile[r * 32 + g] = cn;
                hw[(size_t)b * H_ + g0 + g] = __float2half(hn);
                out[((size_t)b * T_ + t) * H_ + g0 + g] = hn;
            }
            __syncthreads();
        }

        // Barrier arrive (h writes of this step released; last __syncthreads
        // above orders all threads' stores before tid0's release)
        if (t + 1 < T_) {
            if (tid == 0) {
                asm volatile("red.release.gpu.global.add.u32 [%0], 1;"
                             :: "l"(&g_bar_count) : "memory");
            }
        }
    }
}

// ---------------------------------------------------------------------------
// Prep kernels
// ---------------------------------------------------------------------------
__global__ void transpose_interleave_h_kernel(const float* __restrict__ in,
                                              __half* __restrict__ outp,
                                              int ko) {
    __shared__ float tile[32][33];
    int x0 = blockIdx.x * 32, y0 = blockIdx.y * 32;
    #pragma unroll
    for (int i = 0; i < 32; i += 8)
        tile[threadIdx.y + i][threadIdx.x] =
            in[(size_t)(y0 + threadIdx.y + i) * N4H + x0 + threadIdx.x];
    __syncthreads();
    #pragma unroll
    for (int i = 0; i < 32; i += 8) {
        int n = x0 + threadIdx.y + i;
        int nn = ((n & (H_ - 1)) << 2) | (n >> 9);
        int k = y0 + threadIdx.x;
        outp[(size_t)nn * KTOT + ko + k] =
            __float2half(tile[threadIdx.x][threadIdx.y + i]);
    }
}

__global__ void convert_x_kernel(const float4* __restrict__ x,
                                 uint4* __restrict__ xh) {
    size_t i = (size_t)blockIdx.x * blockDim.x + threadIdx.x;
    if (i >= (size_t)B_ * T_ * D_ / 8) return;
    float4 v0 = x[2 * i], v1 = x[2 * i + 1];
    __half2 h0 = __floats2half2_rn(v0.x, v0.y);
    __half2 h1 = __floats2half2_rn(v0.z, v0.w);
    __half2 h2 = __floats2half2_rn(v1.x, v1.y);
    __half2 h3 = __floats2half2_rn(v1.z, v1.w);
    uint4 o;
    o.x = *reinterpret_cast<uint32_t*>(&h0);
    o.y = *reinterpret_cast<uint32_t*>(&h1);
    o.z = *reinterpret_cast<uint32_t*>(&h2);
    o.w = *reinterpret_cast<uint32_t*>(&h3);
    xh[i] = o;
}

__global__ void bias_interleave_kernel(const float* __restrict__ bias,
                                       float* __restrict__ bil) {
    int nn = blockIdx.x * blockDim.x + threadIdx.x;
    if (nn < N4H) bil[nn] = bias[(nn >> 2) + (nn & 3) * H_];
}

__global__ void init_kernel(uint4* __restrict__ h0, unsigned int* barc) {
    int idx = blockIdx.x * blockDim.x + threadIdx.x;
    uint4 z = {0u, 0u, 0u, 0u};
    if (idx < B_ * H_ / 8) h0[idx] = z;
    if (idx == 0) *barc = 0;
}

// ---------------------------------------------------------------------------
// Launch
// ---------------------------------------------------------------------------
extern "C" void kernel_launch(void* const* d_in, const int* in_sizes, int n_in,
                              void* d_out, int out_size)
{
    const float* x    = (const float*)d_in[0];  // [B, T, D]
    const float* W    = (const float*)d_in[1];  // [D, 4H]
    const float* U    = (const float*)d_in[2];  // [H, 4H]
    const float* bias = (const float*)d_in[3];  // [4H]
    float* out = (float*)d_out;                 // [B, T, H]

    __half *wuth, *xh, *h2h;
    float* bil;
    unsigned int* barc;
    cudaGetSymbolAddress((void**)&wuth, g_wuth);
    cudaGetSymbolAddress((void**)&xh,   g_xh);
    cudaGetSymbolAddress((void**)&h2h,  g_h2h);
    cudaGetSymbolAddress((void**)&bil,  g_bias_il);
    cudaGetSymbolAddress((void**)&barc, g_bar_count);
    __half* h0 = h2h;
    __half* h1 = h2h + (size_t)B_ * H_;

    cudaFuncSetAttribute(lstm_persistent_kernel,
                         cudaFuncAttributeMaxDynamicSharedMemorySize, SM_BYTES);

    // Prep
    {
        dim3 blk(32, 8);
        dim3 grdW(N4H / 32, D_ / 32);
        dim3 grdU(N4H / 32, H_ / 32);
        transpose_interleave_h_kernel<<<grdW, blk>>>(W, wuth, 0);
        transpose_interleave_h_kernel<<<grdU, blk>>>(U, wuth, D_);
        bias_interleave_kernel<<<N4H / 256, 256>>>(bias, bil);
        size_t nx8 = (size_t)B_ * T_ * D_ / 8;
        convert_x_kernel<<<(unsigned)((nx8 + 255) / 256), 256>>>(
            (const float4*)x, (uint4*)xh);
        init_kernel<<<(B_ * H_ / 8 + 255) / 256, 256>>>((uint4*)h0, barc);
    }

    lstm_persistent_kernel<<<NCTA, NTHR, SM_BYTES>>>(xh, wuth, bil, h0, h1, out);
}